// round 10
// baseline (speedup 1.0000x reference)
#include <cuda_runtime.h>
#include <cuda_bf16.h>
#include <cstdint>

// Problem constants: B=8, NWIN=256, N=64 tok, C=192, H=6, d=32
#define KT 16
typedef unsigned long long ull;

// ---------------- device scratch (no runtime allocation) ----------------
__device__ float g_wT [192*576];            // qkv_w transposed: [k][o]
__device__ float g_pwT[192*192];            // proj_w transposed: [k][o]
__device__ float g_v  [8*192*256*64];       // V: [b][c][win][tok]; overwritten in-place with attn out Y
__device__ float g_qg [8*192*256];          // [b][c][win]
__device__ float g_kg [8*192*256];

// ---------------- f32x2 helpers ----------------
__device__ __forceinline__ ull fma2(ull a, ull b, ull c){
    ull d; asm("fma.rn.f32x2 %0, %1, %2, %3;" : "=l"(d) : "l"(a), "l"(b), "l"(c)); return d;
}
__device__ __forceinline__ ull pack2(float lo, float hi){
    ull d; asm("mov.b64 %0, {%1, %2};" : "=l"(d) : "f"(lo), "f"(hi)); return d;
}
__device__ __forceinline__ float2 unpack2(ull v){
    float2 r; asm("mov.b64 {%0, %1}, %2;" : "=f"(r.x), "=f"(r.y) : "l"(v)); return r;
}

// Microtile step: 2 toks (tx, tx+32) x 24 outs, one k.
// xs layout [tok][193] (k-major access); wrow = 24 contiguous outs, warp-uniform (broadcast LDS).
__device__ __forceinline__ void mma_step(const float* __restrict__ xs, int k, int tx,
                                         const float* __restrict__ wrow,
                                         ull acc0[12], ull acc1[12]){
    float x0 = xs[ tx      *193 + k];
    float x1 = xs[(tx + 32)*193 + k];
    ull xd0 = pack2(x0, x0);
    ull xd1 = pack2(x1, x1);
    ulonglong2 wA = *(const ulonglong2*)(wrow);
    ulonglong2 wB = *(const ulonglong2*)(wrow + 4);
    ulonglong2 wC = *(const ulonglong2*)(wrow + 8);
    ulonglong2 wD = *(const ulonglong2*)(wrow + 12);
    ulonglong2 wE = *(const ulonglong2*)(wrow + 16);
    ulonglong2 wF = *(const ulonglong2*)(wrow + 20);
    ull wp[12] = {wA.x, wA.y, wB.x, wB.y, wC.x, wC.y,
                  wD.x, wD.y, wE.x, wE.y, wF.x, wF.y};
    #pragma unroll
    for (int p = 0; p < 12; p++){
        acc0[p] = fma2(xd0, wp[p], acc0[p]);
        acc1[p] = fma2(xd1, wp[p], acc1[p]);
    }
}

// ---------------- kernel T: weight transpose to k-major ----------------
__global__ void kTrans(const float* __restrict__ qkv_w, const float* __restrict__ proj_w){
    int idx = blockIdx.x * 256 + threadIdx.x;
    if (idx < 576*192){ int o = idx / 192, k = idx % 192; g_wT [k*576 + o] = qkv_w [idx]; }
    if (idx < 192*192){ int o = idx / 192, k = idx % 192; g_pwT[k*192 + o] = proj_w[idx]; }
}

// ---------------- kernel A: QKV GEMM + grad magnitudes + V scatter ----------------
// smem: xs[64][193], ws[KT][192], qs[64][193]
#define SMEM_A ((64*193 + KT*192 + 64*193) * 4)

__global__ void __launch_bounds__(256, 2) kQKV(const float* __restrict__ x,
                                               const float* __restrict__ qkv_b){
    extern __shared__ float sm[];
    float* xs = sm;                  // [64][193]
    float* ws = sm + 64*193;         // [KT][192]
    float* qs = ws + KT*192;         // [64][193]
    const int tid = threadIdx.x;
    const int blk = blockIdx.x;      // b*256 + win
    const int b   = blk >> 8;
    const int win = blk & 255;
    const float* xw = x + (size_t)blk * (64*192);

    // load x window [tok][192] -> xs[tok][193] (float4 LDG + scalar STS: 193-pitch
    // rows are not 16B-aligned; wide STS would trap)
    #pragma unroll
    for (int it = 0; it < 12; it++){
        int idx = it*256 + tid;           // 0..3071 = 64 tok * 48 quads
        int tok = idx / 48, c4 = idx % 48;
        float4 v = *(const float4*)(xw + tok*192 + c4*4);
        float* dst = xs + tok*193 + c4*4;
        dst[0] = v.x; dst[1] = v.y; dst[2] = v.z; dst[3] = v.w;
    }

    const int tx = tid & 31, ty = tid >> 5;
    const int obase = ty * 24;           // 24 outs per thread, warp-uniform

    for (int s = 0; s < 3; s++){         // q, k, v chunks (192 outs each)
        ull acc0[12], acc1[12];
        {
            const float* bp = qkv_b + s*192 + obase;
            #pragma unroll
            for (int p = 0; p < 12; p++){
                ull bb = pack2(bp[2*p], bp[2*p+1]);
                acc0[p] = bb; acc1[p] = bb;
            }
        }
        for (int kt = 0; kt < 192/KT; kt++){
            __syncthreads();             // xs ready / prev ws & qs consumers done
            #pragma unroll
            for (int it = 0; it < 3; it++){   // stage ws tile [KT][192]
                int idx = it*256 + tid;       // 0..767 quads
                int kk = idx / 48, o4 = idx % 48;
                *(float4*)(ws + kk*192 + o4*4) =
                    *(const float4*)(g_wT + (kt*KT+kk)*576 + s*192 + o4*4);
            }
            __syncthreads();
            #pragma unroll
            for (int kk = 0; kk < KT; kk++)
                mma_step(xs, kt*KT+kk, tx, ws + kk*192 + obase, acc0, acc1);
        }
        __syncthreads();
        // write chunk to qs[tok][193] (scalar stores; 32 lanes hit distinct banks)
        #pragma unroll
        for (int p = 0; p < 12; p++){
            float2 v0 = unpack2(acc0[p]);
            float2 v1 = unpack2(acc1[p]);
            float* q0 = qs +  tx      *193 + obase + 2*p;
            float* q1 = qs + (tx + 32)*193 + obase + 2*p;
            q0[0] = v0.x; q0[1] = v0.y;
            q1[0] = v1.x; q1[1] = v1.y;
        }
        __syncthreads();
        if (s < 2){
            // grad magnitude per channel: 8x8 spatial, zero-padded forward diff
            if (tid < 192){
                float up[8];
                float sum = 0.f;
                #pragma unroll
                for (int yy = 0; yy < 8; yy++){
                    float left = 0.f;
                    #pragma unroll
                    for (int xx = 0; xx < 8; xx++){
                        float cur = qs[(yy*8 + xx)*193 + tid];
                        sum += fabsf(cur - left) + fabsf(cur - (yy ? up[xx] : 0.f));
                        left = cur; up[xx] = cur;
                    }
                }
                if (s == 0) g_qg[(b*192 + tid)*256 + win] = sum * 0.17677669529663687f; // *d^-0.5
                else        g_kg[(b*192 + tid)*256 + win] = sum;
            }
        } else {
            // scatter v -> g_v[b][c][win][tok]
            #pragma unroll
            for (int it = 0; it < 12; it++){
                int idx = it*256 + tid;       // 0..3071 = 192 ch * 16 tok-quads
                int o = idx / 16, t4 = idx % 16;
                float4 v;
                v.x = qs[(t4*4+0)*193 + o];
                v.y = qs[(t4*4+1)*193 + o];
                v.z = qs[(t4*4+2)*193 + o];
                v.w = qs[(t4*4+3)*193 + o];
                *(float4*)(g_v + ((size_t)(b*192 + o)*256 + win)*64 + t4*4) = v;
            }
        }
    }
}

// ---------------- kernel B: softmax(rank-1 scores) @ V per (b, channel) ----------
// smem: vsm[256][64], e64[64][260], qgs[256], red[256], rden[64]
#define EP 260
#define SMEM_B ((16384 + 64*EP + 256 + 256 + 64) * 4)

__global__ void __launch_bounds__(256, 1) kAttn(){
    extern __shared__ float sm[];
    float* vsm  = sm;                 // [256 win][64 tok]
    float* e64  = sm + 16384;         // [64 i][EP]
    float* qgs  = e64 + 64*EP;        // [256]
    float* red  = qgs + 256;          // [256]
    float* rden = red + 256;          // [64]
    const int tid = threadIdx.x;
    const int bc  = blockIdx.x;       // b*192 + c
    const size_t base = (size_t)bc * 256;
    float* vg = g_v + base * 64;

    #pragma unroll
    for (int it = 0; it < 16; it++){
        int idx = it*256 + tid;
        *(float4*)(vsm + idx*4) = *(const float4*)(vg + idx*4);
    }
    qgs[tid] = g_qg[base + tid];
    float kg = g_kg[base + tid];
    red[tid] = kg;
    __syncthreads();
    #pragma unroll
    for (int off = 128; off >= 1; off >>= 1){
        if (tid < off) red[tid] = fmaxf(red[tid], red[tid + off]);
        __syncthreads();
    }
    const float kv = kg - red[0];     // kg_j - kg_max  (<= 0), j = tid

    const int i0  = tid >> 3;         // V-pass: rows i0 and i0+32 of the 64-row block
    const int oct = tid & 7;          // token octet: toks oct*8..+7
    const int iD  = tid >> 2;         // denom: row (0..63)
    const int seg = tid & 3;          // denom: 64-j segment
    const int rot = (iD + seg*8) & 63;   // bank-conflict-free rotation (5*diD+8*dseg !=0 mod 32)

    for (int rb = 0; rb < 4; rb++){
        __syncthreads();              // previous e64 consumers done
        const float* qrow = qgs + rb*64;
        #pragma unroll
        for (int r = 0; r < 64; r++)
            e64[r*EP + tid] = __expf(qrow[r] * kv);
        __syncthreads();
        {   // denominators: 4 rotated 64-j segments per row
            const float* er = e64 + iD*EP + seg*64;
            float ssum = 0.f;
            #pragma unroll
            for (int jj = 0; jj < 64; jj++)
                ssum += er[(jj + rot) & 63];
            red[tid] = ssum;
        }
        __syncthreads();
        if (tid < 64)
            rden[tid] = 1.f / (red[tid*4] + red[tid*4+1] + red[tid*4+2] + red[tid*4+3]);
        __syncthreads();
        {   // weighted V: two rows share every V load
            const float* ev0 = e64 +  i0      *EP;
            const float* ev1 = e64 + (i0 + 32)*EP;
            ull a0[4] = {0,0,0,0};
            ull a1[4] = {0,0,0,0};
            for (int j4 = 0; j4 < 256; j4 += 4){
                float4 e0q = *(const float4*)(ev0 + j4);
                float4 e1q = *(const float4*)(ev1 + j4);
                #pragma unroll
                for (int u = 0; u < 4; u++){
                    float e0 = (u==0)?e0q.x:(u==1)?e0q.y:(u==2)?e0q.z:e0q.w;
                    float e1 = (u==0)?e1q.x:(u==1)?e1q.y:(u==2)?e1q.z:e1q.w;
                    ull ed0 = pack2(e0, e0);
                    ull ed1 = pack2(e1, e1);
                    const float* vr = vsm + (j4 + u)*64 + oct*8;
                    ulonglong2 v0 = *(const ulonglong2*)(vr);
                    ulonglong2 v1 = *(const ulonglong2*)(vr + 4);
                    a0[0] = fma2(ed0, v0.x, a0[0]);
                    a0[1] = fma2(ed0, v0.y, a0[1]);
                    a0[2] = fma2(ed0, v1.x, a0[2]);
                    a0[3] = fma2(ed0, v1.y, a0[3]);
                    a1[0] = fma2(ed1, v0.x, a1[0]);
                    a1[1] = fma2(ed1, v0.y, a1[1]);
                    a1[2] = fma2(ed1, v1.x, a1[2]);
                    a1[3] = fma2(ed1, v1.y, a1[3]);
                }
            }
            float rd0 = rden[i0];
            float rd1 = rden[i0 + 32];
            float* d0 = vg + (size_t)(rb*64 + i0     )*64 + oct*8;
            float* d1 = vg + (size_t)(rb*64 + i0 + 32)*64 + oct*8;
            float2 u0, u1;
            u0 = unpack2(a0[0]); u1 = unpack2(a0[1]);
            *(float4*)(d0)     = make_float4(u0.x*rd0, u0.y*rd0, u1.x*rd0, u1.y*rd0);
            u0 = unpack2(a0[2]); u1 = unpack2(a0[3]);
            *(float4*)(d0 + 4) = make_float4(u0.x*rd0, u0.y*rd0, u1.x*rd0, u1.y*rd0);
            u0 = unpack2(a1[0]); u1 = unpack2(a1[1]);
            *(float4*)(d1)     = make_float4(u0.x*rd1, u0.y*rd1, u1.x*rd1, u1.y*rd1);
            u0 = unpack2(a1[2]); u1 = unpack2(a1[3]);
            *(float4*)(d1 + 4) = make_float4(u0.x*rd1, u0.y*rd1, u1.x*rd1, u1.y*rd1);
        }
    }
}

// ---------------- kernel C: projection GEMM per window ----------------
// smem: ys[64][193], ws[KT][192], qs[64][193]
#define SMEM_C ((64*193 + KT*192 + 64*193) * 4)

__global__ void __launch_bounds__(256, 2) kProj(const float* __restrict__ proj_b,
                                                float* __restrict__ out){
    extern __shared__ float sm[];
    float* ys = sm;                  // [64 tok][193] (k = channel)
    float* ws = sm + 64*193;         // [KT][192]
    float* qs = ws + KT*192;         // [64][193]
    const int tid = threadIdx.x;
    const int blk = blockIdx.x;      // b*256 + win
    const int b   = blk >> 8;
    const int win = blk & 255;

    // gather y: g_v[b][c][win][tok] -> ys[tok][193] (scalar STS; 193-pitch rows)
    #pragma unroll
    for (int it = 0; it < 12; it++){
        int idx = it*256 + tid;           // 0..3071 = 192 ch * 16 tok-quads
        int c = idx / 16, t4 = idx % 16;
        float4 v = *(const float4*)(g_v + ((size_t)(b*192 + c)*256 + win)*64 + t4*4);
        ys[(t4*4+0)*193 + c] = v.x;
        ys[(t4*4+1)*193 + c] = v.y;
        ys[(t4*4+2)*193 + c] = v.z;
        ys[(t4*4+3)*193 + c] = v.w;
    }

    const int tx = tid & 31, ty = tid >> 5;
    const int obase = ty * 24;

    ull acc0[12], acc1[12];
    {
        const float* bp = proj_b + obase;
        #pragma unroll
        for (int p = 0; p < 12; p++){
            ull bb = pack2(bp[2*p], bp[2*p+1]);
            acc0[p] = bb; acc1[p] = bb;
        }
    }
    for (int kt = 0; kt < 192/KT; kt++){
        __syncthreads();
        #pragma unroll
        for (int it = 0; it < 3; it++){
            int idx = it*256 + tid;
            int kk = idx / 48, o4 = idx % 48;
            *(float4*)(ws + kk*192 + o4*4) =
                *(const float4*)(g_pwT + (kt*KT+kk)*192 + o4*4);
        }
        __syncthreads();
        #pragma unroll
        for (int kk = 0; kk < KT; kk++)
            mma_step(ys, kt*KT+kk, tx, ws + kk*192 + obase, acc0, acc1);
    }
    __syncthreads();
    #pragma unroll
    for (int p = 0; p < 12; p++){
        float2 v0 = unpack2(acc0[p]);
        float2 v1 = unpack2(acc1[p]);
        float* q0 = qs +  tx      *193 + obase + 2*p;
        float* q1 = qs + (tx + 32)*193 + obase + 2*p;
        q0[0] = v0.x; q0[1] = v0.y;
        q1[0] = v1.x; q1[1] = v1.y;
    }
    __syncthreads();
    // coalesced store: out[blk][tok][192]
    float* ob = out + (size_t)blk * (64*192);
    #pragma unroll
    for (int it = 0; it < 12; it++){
        int idx = it*256 + tid;           // 0..3071
        int tok = idx / 48, o4 = idx % 48;
        float4 v;
        v.x = qs[tok*193 + o4*4 + 0];
        v.y = qs[tok*193 + o4*4 + 1];
        v.z = qs[tok*193 + o4*4 + 2];
        v.w = qs[tok*193 + o4*4 + 3];
        *(float4*)(ob + tok*192 + o4*4) = v;
    }
}

// ---------------- launch ----------------
extern "C" void kernel_launch(void* const* d_in, const int* in_sizes, int n_in,
                              void* d_out, int out_size){
    const float* x      = (const float*)d_in[0];
    const float* qkv_w  = (const float*)d_in[1];
    const float* qkv_b  = (const float*)d_in[2];
    const float* proj_w = (const float*)d_in[3];
    const float* proj_b = (const float*)d_in[4];
    float* out = (float*)d_out;

    cudaFuncSetAttribute(kQKV,  cudaFuncAttributeMaxDynamicSharedMemorySize, SMEM_A);
    cudaFuncSetAttribute(kAttn, cudaFuncAttributeMaxDynamicSharedMemorySize, SMEM_B);
    cudaFuncSetAttribute(kProj, cudaFuncAttributeMaxDynamicSharedMemorySize, SMEM_C);

    kTrans<<<432, 256>>>(qkv_w, proj_w);
    kQKV <<<2048, 256, SMEM_A>>>(x, qkv_b);
    kAttn<<<1536, 256, SMEM_B>>>();
    kProj<<<2048, 256, SMEM_C>>>(proj_b, out);
}

// round 16
// speedup vs baseline: 1.5902x; 1.5902x over previous
#include <cuda_runtime.h>
#include <cuda_bf16.h>
#include <cstdint>

// Problem constants: B=8, NWIN=256, N=64 tok, C=192, H=6, d=32
#define KT 16
typedef unsigned long long ull;

// ---------------- device scratch (no runtime allocation) ----------------
__device__ float g_wT [192*576];            // qkv_w transposed: [k][o]
__device__ float g_pwT[192*192];            // proj_w transposed: [k][o]
__device__ float g_v  [8*192*256*64];       // V: [b][c][win][tok]; overwritten in-place with attn out Y
__device__ float g_qg [8*192*256];          // [b][c][win]  (pre-scaled by d^-0.5)
__device__ float g_kg [8*192*256];

// ---------------- f32x2 / math helpers ----------------
__device__ __forceinline__ ull fma2(ull a, ull b, ull c){
    ull d; asm("fma.rn.f32x2 %0, %1, %2, %3;" : "=l"(d) : "l"(a), "l"(b), "l"(c)); return d;
}
__device__ __forceinline__ ull pack2(float lo, float hi){
    ull d; asm("mov.b64 %0, {%1, %2};" : "=l"(d) : "f"(lo), "f"(hi)); return d;
}
__device__ __forceinline__ float2 unpack2(ull v){
    float2 r; asm("mov.b64 {%0, %1}, %2;" : "=f"(r.x), "=f"(r.y) : "l"(v)); return r;
}
__device__ __forceinline__ float ex2(float x){
    float y; asm("ex2.approx.ftz.f32 %0, %1;" : "=f"(y) : "f"(x)); return y;
}

// Microtile step (16x16 layout): 4 toks {tx+16t} x 12 outs, one k.
// xs layout [tok][193]; wrow = 12 contiguous outs.
__device__ __forceinline__ void mma_step(const float* __restrict__ xs, int k, int tx,
                                         const float* __restrict__ wrow, ull acc[4][6]){
    ull xd[4];
    #pragma unroll
    for (int t = 0; t < 4; t++){
        float xv = xs[(tx + t*16)*193 + k];
        xd[t] = pack2(xv, xv);
    }
    ulonglong2 wA = *(const ulonglong2*)(wrow);
    ulonglong2 wB = *(const ulonglong2*)(wrow + 4);
    ulonglong2 wC = *(const ulonglong2*)(wrow + 8);
    ull wp[6] = {wA.x, wA.y, wB.x, wB.y, wC.x, wC.y};
    #pragma unroll
    for (int t = 0; t < 4; t++)
        #pragma unroll
        for (int p = 0; p < 6; p++)
            acc[t][p] = fma2(xd[t], wp[p], acc[t][p]);
}

// prefetch one KT x 192 weight tile (row stride 'stride') into 3 float4 regs
__device__ __forceinline__ void loadW(float4 pre[3], const float* __restrict__ gsrc,
                                      int stride, int tid){
    #pragma unroll
    for (int it = 0; it < 3; it++){
        int idx = it*256 + tid;              // 0..767 quads
        int kk = idx / 48, o4 = idx % 48;
        pre[it] = *(const float4*)(gsrc + kk*stride + o4*4);
    }
}
__device__ __forceinline__ void stsW(const float4 pre[3], float* __restrict__ ws, int tid){
    #pragma unroll
    for (int it = 0; it < 3; it++){
        int idx = it*256 + tid;
        int kk = idx / 48, o4 = idx % 48;
        *(float4*)(ws + kk*192 + o4*4) = pre[it];
    }
}

// ---------------- kernel T: weight transpose to k-major ----------------
__global__ void kTrans(const float* __restrict__ qkv_w, const float* __restrict__ proj_w){
    int idx = blockIdx.x * 256 + threadIdx.x;
    if (idx < 576*192){ int o = idx / 192, k = idx % 192; g_wT [k*576 + o] = qkv_w [idx]; }
    if (idx < 192*192){ int o = idx / 192, k = idx % 192; g_pwT[k*192 + o] = proj_w[idx]; }
}

// ---------------- kernel A: QKV GEMM + grad magnitudes + V scatter ----------------
// smem: xs[64][193], ws[KT][192], qs[64][193]
#define SMEM_A ((64*193 + KT*192 + 64*193) * 4)

__global__ void __launch_bounds__(256, 2) kQKV(const float* __restrict__ x,
                                               const float* __restrict__ qkv_b){
    extern __shared__ float sm[];
    float* xs = sm;                  // [64][193]
    float* ws = sm + 64*193;         // [KT][192]
    float* qs = ws + KT*192;         // [64][193]
    const int tid = threadIdx.x;
    const int blk = blockIdx.x;      // b*256 + win
    const int b   = blk >> 8;
    const int win = blk & 255;
    const float* xw = x + (size_t)blk * (64*192);

    // load x window [tok][192] -> xs[tok][193] (float4 LDG + scalar STS; 193-pitch
    // rows are not 16B-aligned, wide STS would trap)
    #pragma unroll
    for (int it = 0; it < 12; it++){
        int idx = it*256 + tid;           // 0..3071 = 64 tok * 48 quads
        int tok = idx / 48, c4 = idx % 48;
        float4 v = *(const float4*)(xw + tok*192 + c4*4);
        float* dst = xs + tok*193 + c4*4;
        dst[0] = v.x; dst[1] = v.y; dst[2] = v.z; dst[3] = v.w;
    }

    const int tx = tid & 15, ty = tid >> 4;
    const int obase = ty * 12;

    float4 pre[3];
    loadW(pre, g_wT, 576, tid);           // tile (s=0, kt=0)

    for (int s = 0; s < 3; s++){          // q, k, v chunks (192 outs each)
        ull acc[4][6];
        {
            const float* bp = qkv_b + s*192 + obase;
            #pragma unroll
            for (int p = 0; p < 6; p++){
                ull bb = pack2(bp[2*p], bp[2*p+1]);
                acc[0][p]=bb; acc[1][p]=bb; acc[2][p]=bb; acc[3][p]=bb;
            }
        }
        for (int kt = 0; kt < 192/KT; kt++){
            __syncthreads();              // ws consumers done (and xs ready on first pass)
            stsW(pre, ws, tid);
            __syncthreads();              // ws tile visible
            if (kt < 11)      loadW(pre, g_wT + (kt+1)*KT*576 + s*192,     576, tid);
            else if (s < 2)   loadW(pre, g_wT +                (s+1)*192,  576, tid);
            #pragma unroll
            for (int kk = 0; kk < KT; kk++)
                mma_step(xs, kt*KT+kk, tx, ws + kk*192 + obase, acc);
        }
        // write chunk to qs[tok][193] (scalar stores; distinct banks across lanes)
        #pragma unroll
        for (int t = 0; t < 4; t++){
            float* q = qs + (tx + t*16)*193 + obase;
            #pragma unroll
            for (int p = 0; p < 6; p++){
                float2 v = unpack2(acc[t][p]);
                q[2*p] = v.x; q[2*p+1] = v.y;
            }
        }
        __syncthreads();
        if (s < 2){
            // grad magnitude per channel: 8x8 spatial, zero-padded forward diff
            if (tid < 192){
                float up[8];
                float sum = 0.f;
                #pragma unroll
                for (int yy = 0; yy < 8; yy++){
                    float left = 0.f;
                    #pragma unroll
                    for (int xx = 0; xx < 8; xx++){
                        float cur = qs[(yy*8 + xx)*193 + tid];
                        sum += fabsf(cur - left) + fabsf(cur - (yy ? up[xx] : 0.f));
                        left = cur; up[xx] = cur;
                    }
                }
                if (s == 0) g_qg[(b*192 + tid)*256 + win] = sum * 0.17677669529663687f; // *d^-0.5
                else        g_kg[(b*192 + tid)*256 + win] = sum;
            }
        } else {
            // scatter v -> g_v[b][c][win][tok]
            #pragma unroll
            for (int it = 0; it < 12; it++){
                int idx = it*256 + tid;       // 0..3071 = 192 ch * 16 tok-quads
                int o = idx / 16, t4 = idx % 16;
                float4 v;
                v.x = qs[(t4*4+0)*193 + o];
                v.y = qs[(t4*4+1)*193 + o];
                v.z = qs[(t4*4+2)*193 + o];
                v.w = qs[(t4*4+3)*193 + o];
                *(float4*)(g_v + ((size_t)(b*192 + o)*256 + win)*64 + t4*4) = v;
            }
        }
    }
}

// ---------------- kernel B: softmax(rank-1 scores) @ V per (b, channel) ----------
// e computed ON THE FLY. Thread owns 8 rows {r0+32m} x 8 toks -> full 256x64 coverage.
// smem: vsm[256][64], kvs[256], qgs[256], den[256], red[256]
#define SMEM_B ((16384 + 4*256) * 4)

__global__ void __launch_bounds__(256, 2) kAttn(){
    extern __shared__ float sm[];
    float* vsm = sm;                  // [256 win][64 tok]
    float* kvs = sm + 16384;          // [256]  kg_j - kgmax
    float* qgs = kvs + 256;           // [256]  qg_i * log2(e)
    float* den = qgs + 256;           // [256]  1/denominator_i
    float* red = den + 256;           // [256]  reduction scratch
    const int tid = threadIdx.x;
    const int bc  = blockIdx.x;       // b*192 + c
    const size_t base = (size_t)bc * 256;
    float* vg = g_v + base * 64;

    #pragma unroll
    for (int it = 0; it < 16; it++){
        int idx = it*256 + tid;
        *(float4*)(vsm + idx*4) = *(const float4*)(vg + idx*4);
    }
    const float LOG2E = 1.4426950408889634f;
    qgs[tid] = g_qg[base + tid] * LOG2E;
    float kg = g_kg[base + tid];
    red[tid] = kg;
    __syncthreads();
    #pragma unroll
    for (int off = 128; off >= 1; off >>= 1){
        if (tid < off) red[tid] = fmaxf(red[tid], red[tid + off]);
        __syncthreads();
    }
    kvs[tid] = kg - red[0];
    __syncthreads();

    // denominators: den_i = 1 / sum_j exp2(qgs_i * kvs_j)   (thread i = tid)
    {
        float qi = qgs[tid];
        float d0 = 0.f, d1 = 0.f, d2 = 0.f, d3 = 0.f;
        for (int j4 = 0; j4 < 256; j4 += 4){
            float4 kq = *(const float4*)(kvs + j4);
            d0 += ex2(qi * kq.x);
            d1 += ex2(qi * kq.y);
            d2 += ex2(qi * kq.z);
            d3 += ex2(qi * kq.w);
        }
        den[tid] = 1.f / ((d0 + d1) + (d2 + d3));
    }
    __syncthreads();

    // V pass: rows {r0 + 32m, m=0..7}, toks oct*8..+7  -> 32 r0 * 8 m = 256 rows
    const int r0  = tid >> 3;         // 0..31
    const int oct = tid & 7;          // 0..7
    float qq[8];
    #pragma unroll
    for (int m = 0; m < 8; m++) qq[m] = qgs[r0 + 32*m];

    ull acc[8][4];
    #pragma unroll
    for (int m = 0; m < 8; m++)
        #pragma unroll
        for (int p = 0; p < 4; p++) acc[m][p] = 0;

    for (int j4 = 0; j4 < 256; j4 += 4){
        float4 kq = *(const float4*)(kvs + j4);
        #pragma unroll
        for (int u = 0; u < 4; u++){
            float kv = (u==0)?kq.x:(u==1)?kq.y:(u==2)?kq.z:kq.w;
            const float* vr = vsm + (j4 + u)*64 + oct*8;
            ulonglong2 v0 = *(const ulonglong2*)(vr);
            ulonglong2 v1 = *(const ulonglong2*)(vr + 4);
            #pragma unroll
            for (int m = 0; m < 8; m++){
                float e = ex2(qq[m] * kv);
                ull ed = pack2(e, e);
                acc[m][0] = fma2(ed, v0.x, acc[m][0]);
                acc[m][1] = fma2(ed, v0.y, acc[m][1]);
                acc[m][2] = fma2(ed, v1.x, acc[m][2]);
                acc[m][3] = fma2(ed, v1.y, acc[m][3]);
            }
        }
    }
    #pragma unroll
    for (int m = 0; m < 8; m++){
        int row = r0 + 32*m;
        float rd = den[row];
        float* dst = vg + (size_t)row*64 + oct*8;   // overwrite g_v in place with Y
        float2 u0 = unpack2(acc[m][0]), u1 = unpack2(acc[m][1]);
        float2 u2 = unpack2(acc[m][2]), u3 = unpack2(acc[m][3]);
        *(float4*)(dst)     = make_float4(u0.x*rd, u0.y*rd, u1.x*rd, u1.y*rd);
        *(float4*)(dst + 4) = make_float4(u2.x*rd, u2.y*rd, u3.x*rd, u3.y*rd);
    }
}

// ---------------- kernel C: projection GEMM per window ----------------
// smem: ys[64][193], ws[KT][192], qs[64][193]
#define SMEM_C ((64*193 + KT*192 + 64*193) * 4)

__global__ void __launch_bounds__(256, 2) kProj(const float* __restrict__ proj_b,
                                                float* __restrict__ out){
    extern __shared__ float sm[];
    float* ys = sm;                  // [64 tok][193] (k = channel)
    float* ws = sm + 64*193;         // [KT][192]
    float* qs = ws + KT*192;         // [64][193]
    const int tid = threadIdx.x;
    const int blk = blockIdx.x;      // b*256 + win
    const int b   = blk >> 8;
    const int win = blk & 255;

    // gather y: g_v[b][c][win][tok] -> ys[tok][193] (scalar STS; 193-pitch rows)
    #pragma unroll
    for (int it = 0; it < 12; it++){
        int idx = it*256 + tid;           // 0..3071 = 192 ch * 16 tok-quads
        int c = idx / 16, t4 = idx % 16;
        float4 v = *(const float4*)(g_v + ((size_t)(b*192 + c)*256 + win)*64 + t4*4);
        ys[(t4*4+0)*193 + c] = v.x;
        ys[(t4*4+1)*193 + c] = v.y;
        ys[(t4*4+2)*193 + c] = v.z;
        ys[(t4*4+3)*193 + c] = v.w;
    }

    const int tx = tid & 15, ty = tid >> 4;
    const int obase = ty * 12;

    float4 pre[3];
    loadW(pre, g_pwT, 192, tid);     // tile kt=0

    ull acc[4][6];
    {
        const float* bp = proj_b + obase;
        #pragma unroll
        for (int p = 0; p < 6; p++){
            ull bb = pack2(bp[2*p], bp[2*p+1]);
            acc[0][p]=bb; acc[1][p]=bb; acc[2][p]=bb; acc[3][p]=bb;
        }
    }
    for (int kt = 0; kt < 192/KT; kt++){
        __syncthreads();
        stsW(pre, ws, tid);
        __syncthreads();
        if (kt < 11) loadW(pre, g_pwT + (kt+1)*KT*192, 192, tid);
        #pragma unroll
        for (int kk = 0; kk < KT; kk++)
            mma_step(ys, kt*KT+kk, tx, ws + kk*192 + obase, acc);
    }
    __syncthreads();
    #pragma unroll
    for (int t = 0; t < 4; t++){
        float* q = qs + (tx + t*16)*193 + obase;
        #pragma unroll
        for (int p = 0; p < 6; p++){
            float2 v = unpack2(acc[t][p]);
            q[2*p] = v.x; q[2*p+1] = v.y;
        }
    }
    __syncthreads();
    // coalesced store: out[blk][tok][192]
    float* ob = out + (size_t)blk * (64*192);
    #pragma unroll
    for (int it = 0; it < 12; it++){
        int idx = it*256 + tid;           // 0..3071
        int tok = idx / 48, o4 = idx % 48;
        float4 v;
        v.x = qs[tok*193 + o4*4 + 0];
        v.y = qs[tok*193 + o4*4 + 1];
        v.z = qs[tok*193 + o4*4 + 2];
        v.w = qs[tok*193 + o4*4 + 3];
        *(float4*)(ob + tok*192 + o4*4) = v;
    }
}

// ---------------- launch ----------------
extern "C" void kernel_launch(void* const* d_in, const int* in_sizes, int n_in,
                              void* d_out, int out_size){
    const float* x      = (const float*)d_in[0];
    const float* qkv_w  = (const float*)d_in[1];
    const float* qkv_b  = (const float*)d_in[2];
    const float* proj_w = (const float*)d_in[3];
    const float* proj_b = (const float*)d_in[4];
    float* out = (float*)d_out;

    cudaFuncSetAttribute(kQKV,  cudaFuncAttributeMaxDynamicSharedMemorySize, SMEM_A);
    cudaFuncSetAttribute(kAttn, cudaFuncAttributeMaxDynamicSharedMemorySize, SMEM_B);
    cudaFuncSetAttribute(kProj, cudaFuncAttributeMaxDynamicSharedMemorySize, SMEM_C);

    kTrans<<<432, 256>>>(qkv_w, proj_w);
    kQKV <<<2048, 256, SMEM_A>>>(x, qkv_b);
    kAttn<<<1536, 256, SMEM_B>>>();
    kProj<<<2048, 256, SMEM_C>>>(proj_b, out);
}